// round 15
// baseline (speedup 1.0000x reference)
#include <cuda_runtime.h>
#include <cuda_bf16.h>
#include <cuda_fp16.h>
#include <cstdint>

#define BB 4
#define SS 1024
#define DM 1024
#define NH 16
#define HD 64

// ---------------- scratch (__device__ globals; no runtime allocation) ----------------
__device__ float g_cos[SS*32];
__device__ float g_sin[SS*32];

__device__ __half gA16h[4194304];                      // hidden fp16
__device__ __half gW16[3145728];                       // Wqkv fp16
__device__ __half gWo16[1048576];                      // Wout fp16
__device__ __half gX16h[4194304];                      // attn output fp16

// attention operands: ALL single fp16
__device__ __half gQ16[4194304];                       // [bh][s][64], pre-scaled 0.125, RoPE'd
__device__ __half gK16[4194304];                       // [bh][s][64], RoPE'd
__device__ __half gV16t[4194304];                      // [bh][d][s]  (transposed V)

// ---------------- helpers ----------------
__device__ __forceinline__ uint32_t smem_u32(const void* p) {
    uint32_t a;
    asm("{ .reg .u64 t; cvta.to.shared.u64 t, %1; cvt.u32.u64 %0, t; }" : "=r"(a) : "l"(p));
    return a;
}
__device__ __forceinline__ void cp16(uint32_t so, const void* g) {
    asm volatile("cp.async.cg.shared.global [%0], [%1], 16;" :: "r"(so), "l"(g));
}
__device__ __forceinline__ void ldmat4(uint32_t* r, uint32_t addr) {
    asm volatile("ldmatrix.sync.aligned.m8n8.x4.shared.b16 {%0,%1,%2,%3}, [%4];"
        : "=r"(r[0]), "=r"(r[1]), "=r"(r[2]), "=r"(r[3]) : "r"(addr));
}
__device__ __forceinline__ void mma16816h(float* c, const uint32_t* a, uint32_t b0, uint32_t b1) {
    asm volatile("mma.sync.aligned.m16n8k16.row.col.f32.f16.f16.f32 "
        "{%0,%1,%2,%3}, {%4,%5,%6,%7}, {%8,%9}, {%0,%1,%2,%3};"
        : "+f"(c[0]), "+f"(c[1]), "+f"(c[2]), "+f"(c[3])
        : "r"(a[0]), "r"(a[1]), "r"(a[2]), "r"(a[3]), "r"(b0), "r"(b1));
}
// fp16x2 pack
__device__ __forceinline__ uint32_t pkh(float lo, float hi) {
    uint32_t r;
    asm("cvt.rn.f16x2.f32 %0, %1, %2;" : "=r"(r) : "f"(hi), "f"(lo));
    return r;
}

// fast exp on FMA/ALU pipes (x <= 0 expected; clamped)
__device__ __forceinline__ float fexp(float x) {
    float y = fmaxf(x, -80.0f) * 1.4426950408889634f;
    float t = y + 12582912.0f;
    int e = (__float_as_int(t) & 0x7FFFFF) - 0x400000;
    float f = y - (t - 12582912.0f);
    float p =      1.3333558146428443e-3f;
    p = fmaf(p, f, 9.6181291076284772e-3f);
    p = fmaf(p, f, 5.5504108664798463e-2f);
    p = fmaf(p, f, 2.4022650695910072e-1f);
    p = fmaf(p, f, 6.9314718055994531e-1f);
    p = fmaf(p, f, 1.0f);
    return __int_as_float(__float_as_int(p) + (e << 23));
}

// ---------------- RoPE table ----------------
__global__ void rope_table_kernel() {
    int idx = blockIdx.x * blockDim.x + threadIdx.x;
    if (idx >= SS * 32) return;
    int pos = idx >> 5;
    int i = idx & 31;
    float inv = powf(10000.0f, -((float)(2 * i)) / 64.0f);
    float t = (float)pos * inv;
    g_cos[idx] = cosf(t);
    g_sin[idx] = sinf(t);
}

// ---------------- fp32 -> fp16 converter ----------------
__global__ void cvt16_kernel(const float* __restrict__ src, int n, int mode) {
    int i = (blockIdx.x * blockDim.x + threadIdx.x) * 4;
    if (i >= n) return;
    float4 v = *(const float4*)&src[i];
    uint32_t h01 = pkh(v.x, v.y);
    uint32_t h23 = pkh(v.z, v.w);
    __half* dst = (mode == 0) ? gA16h : (mode == 1) ? gW16 : gWo16;
    *(uint32_t*)&dst[i]     = h01;
    *(uint32_t*)&dst[i + 2] = h23;
}

// ---------------- fp16 GEMM v3: high-occupancy (8 warps/SMSP) ----------------
// C = A * B^T. CTA 256 thr, tile 64x128; warp tile 16x64 (wm=warp&3, wn=warp>>2).
// acc 32 regs/thread; __launch_bounds__(256,4) caps at 64 regs; 2-stage pipeline,
// stage = A 64x144 (9216) + B 128x144 (18432) = 27648B; 2 buffers, 4 CTAs/SM.
#define GEMM16_SMEM (2 * 27648)

__global__ __launch_bounds__(256, 4) void gemm16(float* __restrict__ C, int mode)
{
    extern __shared__ __align__(128) char sm[];
    const uint32_t sb = smem_u32(sm);
    const int t = threadIdx.x;
    const int lane = t & 31, warp = t >> 5;
    const int wm = warp & 3, wn = warp >> 2;
    const int rowA0 = blockIdx.y * 64;
    const int colB0 = blockIdx.x * 128;

    const __half *Abase, *Bbase;
    if (mode == 1) {
        Abase = gA16h + (size_t)rowA0 * 1024;
        Bbase = gW16 + (size_t)colB0 * 1024;
    } else {
        Abase = gX16h + (size_t)rowA0 * 1024;
        Bbase = gWo16 + (size_t)colB0 * 1024;
    }

    float acc[8][4];
#pragma unroll
    for (int j = 0; j < 8; j++)
#pragma unroll
        for (int k = 0; k < 4; k++) acc[j][k] = 0.f;

    const int arow = (lane & 15);
    const int acol8 = (lane >> 4) * 8;
    const int quad = lane >> 3;
    const int brow_in = (quad >> 1) * 8 + (lane & 7);
    const int bcol8 = (quad & 1) * 8;

    // per stage: A 512 chunks (64r x 8c), B 1024 chunks (128r x 8c); 6 cp16/thread
#define GPREFETCH(s) do {                                                       \
    const uint32_t _sbuf = sb + ((s) & 1) * 27648;                              \
    const int _k0 = (s) * 64;                                                   \
    _Pragma("unroll")                                                           \
    for (int _i = 0; _i < 2; _i++) {                                            \
        int _idx = t + _i * 256;                                                \
        int _r = _idx >> 3, _cb = _idx & 7;                                     \
        cp16(_sbuf + _r * 144 + _cb * 16,                                       \
             Abase + (size_t)_r * 1024 + _k0 + _cb * 8);                        \
    }                                                                           \
    _Pragma("unroll")                                                           \
    for (int _i = 0; _i < 4; _i++) {                                            \
        int _idx = t + _i * 256;                                                \
        int _r = _idx >> 3, _cb = _idx & 7;                                     \
        cp16(_sbuf + 9216 + _r * 144 + _cb * 16,                                \
             Bbase + (size_t)_r * 1024 + _k0 + _cb * 8);                        \
    }                                                                           \
} while (0)

    GPREFETCH(0);
    asm volatile("cp.async.commit_group;");

    for (int s = 0; s < 16; s++) {
        if (s + 1 < 16) {
            GPREFETCH(s + 1);
            asm volatile("cp.async.commit_group;");
            asm volatile("cp.async.wait_group 1;");
        } else {
            asm volatile("cp.async.wait_group 0;");
        }
        __syncthreads();

        const uint32_t sbuf = sb + (s & 1) * 27648;
#pragma unroll
        for (int kk = 0; kk < 64; kk += 16) {
            uint32_t ah[4];
            ldmat4(ah, sbuf + (wm * 16 + arow) * 144 + (kk + acol8) * 2);
#pragma unroll
            for (int ntp = 0; ntp < 4; ntp++) {
                uint32_t bh[4];
                ldmat4(bh, sbuf + 9216 + (wn * 64 + ntp * 16 + brow_in) * 144 + (kk + bcol8) * 2);
                mma16816h(acc[2 * ntp],     ah, bh[0], bh[1]);
                mma16816h(acc[2 * ntp + 1], ah, bh[2], bh[3]);
            }
        }
        __syncthreads();
    }
#undef GPREFETCH

    // ---------------- epilogue ----------------
    const int g = lane >> 2, tq = lane & 3;
#pragma unroll
    for (int nt = 0; nt < 8; nt++) {
        const int col = colB0 + wn * 64 + nt * 8 + tq * 2;
#pragma unroll
        for (int hr = 0; hr < 2; hr++) {
            const int row = rowA0 + wm * 16 + g + hr * 8;
            const float v0 = acc[nt][hr * 2];
            const float v1 = acc[nt][hr * 2 + 1];
            if (mode == 0) {
                *(float2*)&C[(size_t)row * 1024 + col] = make_float2(v0, v1);
            } else {
                const int b = row >> 10, srow = row & 1023;
                const int part = col >> 10, rem = col & 1023;
                const int h = rem >> 6, d = rem & 63;
                const size_t bhbase = (size_t)(b * NH + h) << 16;
                if (part == 2) {
                    gV16t[bhbase + (size_t)d * 1024 + srow]       = __float2half_rn(v0);
                    gV16t[bhbase + (size_t)(d + 1) * 1024 + srow] = __float2half_rn(v1);
                } else {
                    const float co = g_cos[(srow << 5) + (d >> 1)];
                    const float si = g_sin[(srow << 5) + (d >> 1)];
                    float o0 = v0 * co - v1 * si;
                    float o1 = v1 * co + v0 * si;
                    const size_t gb = bhbase + ((size_t)srow << 6) + d;
                    if (part == 0) {
                        *(uint32_t*)&gQ16[gb] = pkh(o0 * 0.125f, o1 * 0.125f);
                    } else {
                        *(uint32_t*)&gK16[gb] = pkh(o0, o1);
                    }
                }
            }
        }
    }
}

// ---------------- flash attention: all-fp16 single-product (unchanged) ----------------
#define ATT_SMEM (9216 + 2 * 18432)

__global__ __launch_bounds__(128) void attn_kernel()
{
    extern __shared__ __align__(128) char sm[];
    const uint32_t sb = smem_u32(sm);
    const int t = threadIdx.x, lane = t & 31, w = t >> 5;
    const int qt = blockIdx.x, bh = blockIdx.y;

    const __half* Q_p  = gQ16  + (size_t)bh * 65536 + qt * 4096;
    const __half* K_b  = gK16  + (size_t)bh * 65536;
    const __half* Vt_b = gV16t + (size_t)bh * 65536;

    const int arow = lane & 15, acol8 = (lane >> 4) * 8;
    const int quad = lane >> 3;
    const int brow = (quad >> 1) * 8 + (lane & 7);
    const int bcol8 = (quad & 1) * 8;
    const int g = lane >> 2, tq = lane & 3;
    const int row0 = w * 16 + g;

#pragma unroll
    for (int i = 0; i < 4; i++) {
        int ch = t + i * 128;
        int r = ch >> 3, cbk = ch & 7;
        cp16(sb + r * 144 + cbk * 16, Q_p + r * 64 + cbk * 8);
    }
    asm volatile("cp.async.commit_group;");

#define LOAD_STAGE(KT) do {                                                   \
    const uint32_t _st = sb + 9216 + ((KT) & 1) * 18432;                      \
    _Pragma("unroll")                                                         \
    for (int _i = 0; _i < 4; _i++) {                                          \
        int _ch = t + _i * 128;                                               \
        int _r = _ch >> 3, _cb = _ch & 7;                                     \
        uint32_t _off = _r * 144 + _cb * 16;                                  \
        size_t _gk = (size_t)(KT) * 4096 + _r * 64 + _cb * 8;                 \
        size_t _gv = (size_t)_r * 1024 + (KT) * 64 + _cb * 8;                 \
        cp16(_st + _off,        K_b + _gk);                                   \
        cp16(_st + 9216 + _off, Vt_b + _gv);                                  \
    }                                                                         \
} while (0)

    LOAD_STAGE(0);
    asm volatile("cp.async.commit_group;");

    float m0 = -1e30f, m1 = -1e30f, l0 = 0.f, l1 = 0.f;
    float o[8][4];
#pragma unroll
    for (int nt = 0; nt < 8; nt++)
#pragma unroll
        for (int j = 0; j < 4; j++) o[nt][j] = 0.f;
    uint32_t qf[4][4];

    for (int kt = 0; kt <= qt; kt++) {
        if (kt + 1 <= qt) {
            LOAD_STAGE(kt + 1);
            asm volatile("cp.async.commit_group;");
            asm volatile("cp.async.wait_group 1;");
        } else {
            asm volatile("cp.async.wait_group 0;");
        }
        __syncthreads();

        if (kt == 0) {
#pragma unroll
            for (int c = 0; c < 4; c++) {
                uint32_t qa = sb + (w * 16 + arow) * 144 + (c * 16 + acol8) * 2;
                ldmat4(qf[c], qa);
            }
        }

        const uint32_t ST = sb + 9216 + (kt & 1) * 18432;
        const uint32_t KH = ST, VTH = ST + 9216;

        float sc[8][4];
#pragma unroll
        for (int nt = 0; nt < 8; nt++)
#pragma unroll
            for (int j = 0; j < 4; j++) sc[nt][j] = 0.f;

#pragma unroll
        for (int c = 0; c < 4; c++) {
#pragma unroll
            for (int np = 0; np < 4; np++) {
                uint32_t k4[4];
                uint32_t ka = KH + (np * 16 + brow) * 144 + (c * 16 + bcol8) * 2;
                ldmat4(k4, ka);
                mma16816h(sc[2 * np],     qf[c], k4[0], k4[1]);
                mma16816h(sc[2 * np + 1], qf[c], k4[2], k4[3]);
            }
        }

        if (kt == qt) {
#pragma unroll
            for (int nt = 0; nt < 8; nt++) {
                int cbase = nt * 8 + tq * 2;
                if (cbase     > row0)     sc[nt][0] = -1e30f;
                if (cbase + 1 > row0)     sc[nt][1] = -1e30f;
                if (cbase     > row0 + 8) sc[nt][2] = -1e30f;
                if (cbase + 1 > row0 + 8) sc[nt][3] = -1e30f;
            }
        }

        float mt0 = sc[0][0], mt1 = sc[0][2];
#pragma unroll
        for (int nt = 0; nt < 8; nt++) {
            mt0 = fmaxf(mt0, fmaxf(sc[nt][0], sc[nt][1]));
            mt1 = fmaxf(mt1, fmaxf(sc[nt][2], sc[nt][3]));
        }
        mt0 = fmaxf(mt0, __shfl_xor_sync(0xffffffffu, mt0, 1));
        mt0 = fmaxf(mt0, __shfl_xor_sync(0xffffffffu, mt0, 2));
        mt1 = fmaxf(mt1, __shfl_xor_sync(0xffffffffu, mt1, 1));
        mt1 = fmaxf(mt1, __shfl_xor_sync(0xffffffffu, mt1, 2));
        float mn0 = fmaxf(m0, mt0), mn1 = fmaxf(m1, mt1);
        float a0 = fexp(m0 - mn0), a1 = fexp(m1 - mn1);
        m0 = mn0; m1 = mn1;
        float s0 = 0.f, s1 = 0.f;
#pragma unroll
        for (int nt = 0; nt < 8; nt++) {
            sc[nt][0] = fexp(sc[nt][0] - m0); s0 += sc[nt][0];
            sc[nt][1] = fexp(sc[nt][1] - m0); s0 += sc[nt][1];
            sc[nt][2] = fexp(sc[nt][2] - m1); s1 += sc[nt][2];
            sc[nt][3] = fexp(sc[nt][3] - m1); s1 += sc[nt][3];
        }
        s0 += __shfl_xor_sync(0xffffffffu, s0, 1);
        s0 += __shfl_xor_sync(0xffffffffu, s0, 2);
        s1 += __shfl_xor_sync(0xffffffffu, s1, 1);
        s1 += __shfl_xor_sync(0xffffffffu, s1, 2);
        l0 = l0 * a0 + s0;
        l1 = l1 * a1 + s1;
#pragma unroll
        for (int nt = 0; nt < 8; nt++) {
            o[nt][0] *= a0; o[nt][1] *= a0;
            o[nt][2] *= a1; o[nt][3] *= a1;
        }

#pragma unroll
        for (int c = 0; c < 4; c++) {
            const float* pa = sc[2 * c];
            const float* pb = sc[2 * c + 1];
            uint32_t pah[4];
            pah[0] = pkh(pa[0], pa[1]);
            pah[1] = pkh(pa[2], pa[3]);
            pah[2] = pkh(pb[0], pb[1]);
            pah[3] = pkh(pb[2], pb[3]);
#pragma unroll
            for (int np = 0; np < 4; np++) {
                uint32_t vh4[4];
                uint32_t va = VTH + (np * 16 + brow) * 144 + (c * 16 + bcol8) * 2;
                ldmat4(vh4, va);
                mma16816h(o[2 * np],     pah, vh4[0], vh4[1]);
                mma16816h(o[2 * np + 1], pah, vh4[2], vh4[3]);
            }
        }
        __syncthreads();
    }
#undef LOAD_STAGE

    const float il0 = 1.0f / l0, il1 = 1.0f / l1;
    const int b = bh >> 4, h = bh & 15;
    const int sr0 = qt * 64 + w * 16 + g;
    const size_t base0 = ((size_t)((b << 10) + sr0)) * 1024 + h * 64;
    const size_t base1 = base0 + 8 * 1024;
#pragma unroll
    for (int nt = 0; nt < 8; nt++) {
        const int d = nt * 8 + tq * 2;
        *(uint32_t*)&gX16h[base0 + d] = pkh(o[nt][0] * il0, o[nt][1] * il0);
        *(uint32_t*)&gX16h[base1 + d] = pkh(o[nt][2] * il1, o[nt][3] * il1);
    }
}

// ---------------- launch ----------------
extern "C" void kernel_launch(void* const* d_in, const int* in_sizes, int n_in,
                              void* d_out, int out_size)
{
    const float* hidden = (const float*)d_in[0];
    const float* Wqkv = (const float*)d_in[3];
    const float* Wout = (const float*)d_in[4];
    float* out = (float*)d_out;

    cudaFuncSetAttribute(gemm16, cudaFuncAttributeMaxDynamicSharedMemorySize, GEMM16_SMEM);
    cudaFuncSetAttribute(attn_kernel, cudaFuncAttributeMaxDynamicSharedMemorySize, ATT_SMEM);

    rope_table_kernel<<<128, 256>>>();                      // launch 0
    cvt16_kernel<<<4096, 256>>>(hidden, 4194304, 0);        // launch 1
    cvt16_kernel<<<3072, 256>>>(Wqkv, 3145728, 1);          // launch 2
    gemm16<<<dim3(24, 64), 256, GEMM16_SMEM>>>(nullptr, 1); // launch 3 (ncu slot): QKV
    cvt16_kernel<<<1024, 256>>>(Wout, 1048576, 2);          // launch 4
    attn_kernel<<<dim3(16, 64), 128, ATT_SMEM>>>();         // launch 5
    gemm16<<<dim3(8, 64), 256, GEMM16_SMEM>>>(out, 0);      // launch 6: out-proj
}

// round 16
// speedup vs baseline: 1.0553x; 1.0553x over previous
#include <cuda_runtime.h>
#include <cuda_bf16.h>
#include <cuda_fp16.h>
#include <cstdint>

#define BB 4
#define SS 1024
#define DM 1024
#define NH 16
#define HD 64

// ---------------- scratch (__device__ globals; no runtime allocation) ----------------
__device__ float g_cos[SS*32];
__device__ float g_sin[SS*32];

__device__ __half gA16h[4194304];                      // hidden fp16
__device__ __half gW16[3145728];                       // Wqkv fp16
__device__ __half gWo16[1048576];                      // Wout fp16
__device__ __half gX16h[4194304];                      // attn output fp16

// attention operands: ALL single fp16
__device__ __half gQ16[4194304];                       // [bh][s][64], pre-scaled 0.125, RoPE'd
__device__ __half gK16[4194304];                       // [bh][s][64], RoPE'd
__device__ __half gV16t[4194304];                      // [bh][d][s]  (transposed V)

// ---------------- helpers ----------------
__device__ __forceinline__ uint32_t smem_u32(const void* p) {
    uint32_t a;
    asm("{ .reg .u64 t; cvta.to.shared.u64 t, %1; cvt.u32.u64 %0, t; }" : "=r"(a) : "l"(p));
    return a;
}
__device__ __forceinline__ void cp16(uint32_t so, const void* g) {
    asm volatile("cp.async.cg.shared.global [%0], [%1], 16;" :: "r"(so), "l"(g));
}
__device__ __forceinline__ void ldmat4(uint32_t* r, uint32_t addr) {
    asm volatile("ldmatrix.sync.aligned.m8n8.x4.shared.b16 {%0,%1,%2,%3}, [%4];"
        : "=r"(r[0]), "=r"(r[1]), "=r"(r[2]), "=r"(r[3]) : "r"(addr));
}
__device__ __forceinline__ void mma16816h(float* c, const uint32_t* a, uint32_t b0, uint32_t b1) {
    asm volatile("mma.sync.aligned.m16n8k16.row.col.f32.f16.f16.f32 "
        "{%0,%1,%2,%3}, {%4,%5,%6,%7}, {%8,%9}, {%0,%1,%2,%3};"
        : "+f"(c[0]), "+f"(c[1]), "+f"(c[2]), "+f"(c[3])
        : "r"(a[0]), "r"(a[1]), "r"(a[2]), "r"(a[3]), "r"(b0), "r"(b1));
}
// fp16x2 pack
__device__ __forceinline__ uint32_t pkh(float lo, float hi) {
    uint32_t r;
    asm("cvt.rn.f16x2.f32 %0, %1, %2;" : "=r"(r) : "f"(hi), "f"(lo));
    return r;
}

// fast exp on FMA/ALU pipes (x <= 0 expected; clamped)
__device__ __forceinline__ float fexp(float x) {
    float y = fmaxf(x, -80.0f) * 1.4426950408889634f;
    float t = y + 12582912.0f;
    int e = (__float_as_int(t) & 0x7FFFFF) - 0x400000;
    float f = y - (t - 12582912.0f);
    float p =      1.3333558146428443e-3f;
    p = fmaf(p, f, 9.6181291076284772e-3f);
    p = fmaf(p, f, 5.5504108664798463e-2f);
    p = fmaf(p, f, 2.4022650695910072e-1f);
    p = fmaf(p, f, 6.9314718055994531e-1f);
    p = fmaf(p, f, 1.0f);
    return __int_as_float(__float_as_int(p) + (e << 23));
}

// ---------------- fused prep: all fp32->fp16 conversions + RoPE table, ONE launch ----------------
// blocks [0,4096): hidden -> gA16h   (4M elems)
// blocks [4096,7168): Wqkv -> gW16   (3M elems)
// blocks [7168,8192): Wout -> gWo16  (1M elems)
// blocks [8192,8320): RoPE table     (32K entries)
__global__ void prep_kernel(const float* __restrict__ hidden,
                            const float* __restrict__ Wqkv,
                            const float* __restrict__ Wout)
{
    const int blk = blockIdx.x;
    if (blk < 7168 + 1024) {
        const float* src;
        __half* dst;
        int base;
        if (blk < 4096)      { src = hidden; dst = gA16h; base = blk; }
        else if (blk < 7168) { src = Wqkv;   dst = gW16;  base = blk - 4096; }
        else                 { src = Wout;   dst = gWo16; base = blk - 7168; }
        int i = (base * 256 + threadIdx.x) * 4;
        float4 v = *(const float4*)&src[i];
        *(uint32_t*)&dst[i]     = pkh(v.x, v.y);
        *(uint32_t*)&dst[i + 2] = pkh(v.z, v.w);
    } else {
        int idx = (blk - 8192) * 256 + threadIdx.x;
        if (idx < SS * 32) {
            int pos = idx >> 5;
            int i = idx & 31;
            float inv = powf(10000.0f, -((float)(2 * i)) / 64.0f);
            float t = (float)pos * inv;
            g_cos[idx] = cosf(t);
            g_sin[idx] = sinf(t);
        }
    }
}

// ---------------- fp16 single-product GEMM, K-chunk 64 (R14 champion config) ----------------
// C = A * B^T. CTA 128x128, 8 warps 32x64, K-chunk 64, 3-stage pipeline.
// Stage: A@0 (128 rows x 144B), B@18432 (128 rows x 144B) = 36864B.
// mode 1: A=hidden16, B=Wqkv16, RoPE/scatter epilogue. mode 0: A=X16, B=Wout16, write C.
#define GEMM16_SMEM (3 * 36864)

__global__ __launch_bounds__(256, 2) void gemm16(float* __restrict__ C, int mode)
{
    extern __shared__ __align__(128) char sm[];
    const uint32_t sb = smem_u32(sm);
    const int t = threadIdx.x;
    const int lane = t & 31, warp = t >> 5;
    const int wm = warp & 3, wn = warp >> 2;
    const int rowA0 = blockIdx.y * 128;
    const int colB0 = blockIdx.x * 128;

    const __half *Abase, *Bbase;
    if (mode == 1) {
        Abase = gA16h + (size_t)rowA0 * 1024;
        Bbase = gW16 + (size_t)colB0 * 1024;
    } else {
        Abase = gX16h + (size_t)rowA0 * 1024;
        Bbase = gWo16 + (size_t)colB0 * 1024;
    }

    float acc[2][8][4];
#pragma unroll
    for (int i = 0; i < 2; i++)
#pragma unroll
        for (int j = 0; j < 8; j++)
#pragma unroll
            for (int k = 0; k < 4; k++) acc[i][j][k] = 0.f;

    const int arow = (lane & 15);
    const int acol8 = (lane >> 4) * 8;
    const int quad = lane >> 3;
    const int brow_in = (quad >> 1) * 8 + (lane & 7);
    const int bcol8 = (quad & 1) * 8;

#define GPREFETCH(s) do {                                                       \
    const uint32_t _sbuf = sb + ((s) % 3) * 36864;                              \
    const int _k0 = (s) * 64;                                                   \
    _Pragma("unroll")                                                           \
    for (int _i = 0; _i < 4; _i++) {                                            \
        int _idx = t + _i * 256;                                                \
        int _r = _idx >> 3, _cb = _idx & 7;                                     \
        uint32_t _off = _r * 144 + _cb * 16;                                    \
        size_t _go = (size_t)_r * 1024 + _k0 + _cb * 8;                         \
        cp16(_sbuf + _off,          Abase + _go);                               \
        cp16(_sbuf + 18432 + _off,  Bbase + _go);                               \
    }                                                                           \
} while (0)

    GPREFETCH(0);
    asm volatile("cp.async.commit_group;");
    GPREFETCH(1);
    asm volatile("cp.async.commit_group;");

    for (int s = 0; s < 16; s++) {
        if (s + 2 < 16) {
            GPREFETCH(s + 2);
            asm volatile("cp.async.commit_group;");
            asm volatile("cp.async.wait_group 2;");
        } else if (s + 1 < 16) {
            asm volatile("cp.async.wait_group 1;");
        } else {
            asm volatile("cp.async.wait_group 0;");
        }
        __syncthreads();

        const uint32_t sbuf = sb + (s % 3) * 36864;
#pragma unroll
        for (int kk = 0; kk < 64; kk += 16) {
            uint32_t ah[2][4];
#pragma unroll
            for (int mt = 0; mt < 2; mt++) {
                uint32_t aa = sbuf + (wm * 32 + mt * 16 + arow) * 144 + (kk + acol8) * 2;
                ldmat4(ah[mt], aa);
            }
#pragma unroll
            for (int ntp = 0; ntp < 4; ntp++) {
                uint32_t ba = sbuf + 18432 + (wn * 64 + ntp * 16 + brow_in) * 144 + (kk + bcol8) * 2;
                uint32_t bh[4];
                ldmat4(bh, ba);
                mma16816h(acc[0][2 * ntp],     ah[0], bh[0], bh[1]);
                mma16816h(acc[1][2 * ntp],     ah[1], bh[0], bh[1]);
                mma16816h(acc[0][2 * ntp + 1], ah[0], bh[2], bh[3]);
                mma16816h(acc[1][2 * ntp + 1], ah[1], bh[2], bh[3]);
            }
        }
        __syncthreads();
    }
#undef GPREFETCH

    // ---------------- epilogue ----------------
    const int g = lane >> 2, tq = lane & 3;
#pragma unroll
    for (int mt = 0; mt < 2; mt++) {
#pragma unroll
        for (int nt = 0; nt < 8; nt++) {
            const int col = colB0 + wn * 64 + nt * 8 + tq * 2;
#pragma unroll
            for (int hr = 0; hr < 2; hr++) {
                const int row = rowA0 + wm * 32 + mt * 16 + g + hr * 8;
                const float v0 = acc[mt][nt][hr * 2];
                const float v1 = acc[mt][nt][hr * 2 + 1];
                if (mode == 0) {
                    *(float2*)&C[(size_t)row * 1024 + col] = make_float2(v0, v1);
                } else {
                    const int b = row >> 10, srow = row & 1023;
                    const int part = col >> 10, rem = col & 1023;
                    const int h = rem >> 6, d = rem & 63;
                    const size_t bhbase = (size_t)(b * NH + h) << 16;
                    if (part == 2) {
                        gV16t[bhbase + (size_t)d * 1024 + srow]       = __float2half_rn(v0);
                        gV16t[bhbase + (size_t)(d + 1) * 1024 + srow] = __float2half_rn(v1);
                    } else {
                        const float co = g_cos[(srow << 5) + (d >> 1)];
                        const float si = g_sin[(srow << 5) + (d >> 1)];
                        float o0 = v0 * co - v1 * si;
                        float o1 = v1 * co + v0 * si;
                        const size_t gb = bhbase + ((size_t)srow << 6) + d;
                        if (part == 0) {
                            *(uint32_t*)&gQ16[gb] = pkh(o0 * 0.125f, o1 * 0.125f);
                        } else {
                            *(uint32_t*)&gK16[gb] = pkh(o0, o1);
                        }
                    }
                }
            }
        }
    }
}

// ---------------- flash attention: all-fp16 single-product (unchanged from R14) ----------------
#define ATT_SMEM (9216 + 2 * 18432)

__global__ __launch_bounds__(128) void attn_kernel()
{
    extern __shared__ __align__(128) char sm[];
    const uint32_t sb = smem_u32(sm);
    const int t = threadIdx.x, lane = t & 31, w = t >> 5;
    const int qt = blockIdx.x, bh = blockIdx.y;

    const __half* Q_p  = gQ16  + (size_t)bh * 65536 + qt * 4096;
    const __half* K_b  = gK16  + (size_t)bh * 65536;
    const __half* Vt_b = gV16t + (size_t)bh * 65536;

    const int arow = lane & 15, acol8 = (lane >> 4) * 8;
    const int quad = lane >> 3;
    const int brow = (quad >> 1) * 8 + (lane & 7);
    const int bcol8 = (quad & 1) * 8;
    const int g = lane >> 2, tq = lane & 3;
    const int row0 = w * 16 + g;

#pragma unroll
    for (int i = 0; i < 4; i++) {
        int ch = t + i * 128;
        int r = ch >> 3, cbk = ch & 7;
        cp16(sb + r * 144 + cbk * 16, Q_p + r * 64 + cbk * 8);
    }
    asm volatile("cp.async.commit_group;");

#define LOAD_STAGE(KT) do {                                                   \
    const uint32_t _st = sb + 9216 + ((KT) & 1) * 18432;                      \
    _Pragma("unroll")                                                         \
    for (int _i = 0; _i < 4; _i++) {                                          \
        int _ch = t + _i * 128;                                               \
        int _r = _ch >> 3, _cb = _ch & 7;                                     \
        uint32_t _off = _r * 144 + _cb * 16;                                  \
        size_t _gk = (size_t)(KT) * 4096 + _r * 64 + _cb * 8;                 \
        size_t _gv = (size_t)_r * 1024 + (KT) * 64 + _cb * 8;                 \
        cp16(_st + _off,        K_b + _gk);                                   \
        cp16(_st + 9216 + _off, Vt_b + _gv);                                  \
    }                                                                         \
} while (0)

    LOAD_STAGE(0);
    asm volatile("cp.async.commit_group;");

    float m0 = -1e30f, m1 = -1e30f, l0 = 0.f, l1 = 0.f;
    float o[8][4];
#pragma unroll
    for (int nt = 0; nt < 8; nt++)
#pragma unroll
        for (int j = 0; j < 4; j++) o[nt][j] = 0.f;
    uint32_t qf[4][4];

    for (int kt = 0; kt <= qt; kt++) {
        if (kt + 1 <= qt) {
            LOAD_STAGE(kt + 1);
            asm volatile("cp.async.commit_group;");
            asm volatile("cp.async.wait_group 1;");
        } else {
            asm volatile("cp.async.wait_group 0;");
        }
        __syncthreads();

        if (kt == 0) {
#pragma unroll
            for (int c = 0; c < 4; c++) {
                uint32_t qa = sb + (w * 16 + arow) * 144 + (c * 16 + acol8) * 2;
                ldmat4(qf[c], qa);
            }
        }

        const uint32_t ST = sb + 9216 + (kt & 1) * 18432;
        const uint32_t KH = ST, VTH = ST + 9216;

        float sc[8][4];
#pragma unroll
        for (int nt = 0; nt < 8; nt++)
#pragma unroll
            for (int j = 0; j < 4; j++) sc[nt][j] = 0.f;

#pragma unroll
        for (int c = 0; c < 4; c++) {
#pragma unroll
            for (int np = 0; np < 4; np++) {
                uint32_t k4[4];
                uint32_t ka = KH + (np * 16 + brow) * 144 + (c * 16 + bcol8) * 2;
                ldmat4(k4, ka);
                mma16816h(sc[2 * np],     qf[c], k4[0], k4[1]);
                mma16816h(sc[2 * np + 1], qf[c], k4[2], k4[3]);
            }
        }

        if (kt == qt) {
#pragma unroll
            for (int nt = 0; nt < 8; nt++) {
                int cbase = nt * 8 + tq * 2;
                if (cbase     > row0)     sc[nt][0] = -1e30f;
                if (cbase + 1 > row0)     sc[nt][1] = -1e30f;
                if (cbase     > row0 + 8) sc[nt][2] = -1e30f;
                if (cbase + 1 > row0 + 8) sc[nt][3] = -1e30f;
            }
        }

        float mt0 = sc[0][0], mt1 = sc[0][2];
#pragma unroll
        for (int nt = 0; nt < 8; nt++) {
            mt0 = fmaxf(mt0, fmaxf(sc[nt][0], sc[nt][1]));
            mt1 = fmaxf(mt1, fmaxf(sc[nt][2], sc[nt][3]));
        }
        mt0 = fmaxf(mt0, __shfl_xor_sync(0xffffffffu, mt0, 1));
        mt0 = fmaxf(mt0, __shfl_xor_sync(0xffffffffu, mt0, 2));
        mt1 = fmaxf(mt1, __shfl_xor_sync(0xffffffffu, mt1, 1));
        mt1 = fmaxf(mt1, __shfl_xor_sync(0xffffffffu, mt1, 2));
        float mn0 = fmaxf(m0, mt0), mn1 = fmaxf(m1, mt1);
        float a0 = fexp(m0 - mn0), a1 = fexp(m1 - mn1);
        m0 = mn0; m1 = mn1;
        float s0 = 0.f, s1 = 0.f;
#pragma unroll
        for (int nt = 0; nt < 8; nt++) {
            sc[nt][0] = fexp(sc[nt][0] - m0); s0 += sc[nt][0];
            sc[nt][1] = fexp(sc[nt][1] - m0); s0 += sc[nt][1];
            sc[nt][2] = fexp(sc[nt][2] - m1); s1 += sc[nt][2];
            sc[nt][3] = fexp(sc[nt][3] - m1); s1 += sc[nt][3];
        }
        s0 += __shfl_xor_sync(0xffffffffu, s0, 1);
        s0 += __shfl_xor_sync(0xffffffffu, s0, 2);
        s1 += __shfl_xor_sync(0xffffffffu, s1, 1);
        s1 += __shfl_xor_sync(0xffffffffu, s1, 2);
        l0 = l0 * a0 + s0;
        l1 = l1 * a1 + s1;
#pragma unroll
        for (int nt = 0; nt < 8; nt++) {
            o[nt][0] *= a0; o[nt][1] *= a0;
            o[nt][2] *= a1; o[nt][3] *= a1;
        }

#pragma unroll
        for (int c = 0; c < 4; c++) {
            const float* pa = sc[2 * c];
            const float* pb = sc[2 * c + 1];
            uint32_t pah[4];
            pah[0] = pkh(pa[0], pa[1]);
            pah[1] = pkh(pa[2], pa[3]);
            pah[2] = pkh(pb[0], pb[1]);
            pah[3] = pkh(pb[2], pb[3]);
#pragma unroll
            for (int np = 0; np < 4; np++) {
                uint32_t vh4[4];
                uint32_t va = VTH + (np * 16 + brow) * 144 + (c * 16 + bcol8) * 2;
                ldmat4(vh4, va);
                mma16816h(o[2 * np],     pah, vh4[0], vh4[1]);
                mma16816h(o[2 * np + 1], pah, vh4[2], vh4[3]);
            }
        }
        __syncthreads();
    }
#undef LOAD_STAGE

    const float il0 = 1.0f / l0, il1 = 1.0f / l1;
    const int b = bh >> 4, h = bh & 15;
    const int sr0 = qt * 64 + w * 16 + g;
    const size_t base0 = ((size_t)((b << 10) + sr0)) * 1024 + h * 64;
    const size_t base1 = base0 + 8 * 1024;
#pragma unroll
    for (int nt = 0; nt < 8; nt++) {
        const int d = nt * 8 + tq * 2;
        *(uint32_t*)&gX16h[base0 + d] = pkh(o[nt][0] * il0, o[nt][1] * il0);
        *(uint32_t*)&gX16h[base1 + d] = pkh(o[nt][2] * il1, o[nt][3] * il1);
    }
}

// ---------------- launch ----------------
extern "C" void kernel_launch(void* const* d_in, const int* in_sizes, int n_in,
                              void* d_out, int out_size)
{
    const float* hidden = (const float*)d_in[0];
    const float* Wqkv = (const float*)d_in[3];
    const float* Wout = (const float*)d_in[4];
    float* out = (float*)d_out;

    cudaFuncSetAttribute(gemm16, cudaFuncAttributeMaxDynamicSharedMemorySize, GEMM16_SMEM);
    cudaFuncSetAttribute(attn_kernel, cudaFuncAttributeMaxDynamicSharedMemorySize, ATT_SMEM);

    prep_kernel<<<8320, 256>>>(hidden, Wqkv, Wout);         // launch 0: all cvts + RoPE table
    gemm16<<<dim3(24, 32), 256, GEMM16_SMEM>>>(nullptr, 1); // launch 1: QKV + RoPE scatter
    attn_kernel<<<dim3(16, 64), 128, ATT_SMEM>>>();         // launch 2: attention
    gemm16<<<dim3(8, 32), 256, GEMM16_SMEM>>>(out, 0);      // launch 3: out-proj
}